// round 4
// baseline (speedup 1.0000x reference)
#include <cuda_runtime.h>
#include <cuda_bf16.h>
#include <cstdint>

// Problem constants
#define BB   8
#define CIN  128
#define COUT 128
#define HH   128
#define WW   128
#define RNK  32
#define HW   (HH*WW)
#define K3   (3.0f/128.0f)

// Scratch (no allocation allowed)
__device__ float g_vproj[BB*CIN*16];      // (b, i, p*4+q)
__device__ float g_vr[BB*RNK];            // (b, r)
__device__ float g_mpart[4][BB*COUT*16];  // partial m over r-chunks
// conv_w pre-split into MMA A-fragment layout: [prec][o_tile(8)][kstep(8)][lane(32)]
__device__ uint4 g_Wfrag[2][8][8][32];

__device__ __forceinline__ float hatf(float d) {
    return fmaxf(0.0f, 1.0f - fabsf(d));
}

// split x,y into bf16 hi/lo packed pairs (low half = x)
__device__ __forceinline__ void split_pack(float x, float y, uint32_t& hi, uint32_t& lo) {
    __nv_bfloat16 hx = __float2bfloat16(x);
    __nv_bfloat16 hy = __float2bfloat16(y);
    float rx = x - __bfloat162float(hx);
    float ry = y - __bfloat162float(hy);
    __nv_bfloat162 H; H.x = hx; H.y = hy;
    __nv_bfloat162 L; L.x = __float2bfloat16(rx); L.y = __float2bfloat16(ry);
    hi = *reinterpret_cast<uint32_t*>(&H);
    lo = *reinterpret_cast<uint32_t*>(&L);
}

// ============================================================================
// Kernel A: vproj[b,i,p,q] = sum_hw wy[h,p]*wx[w,q]*v[b,i,h,w]
// grid = B*Cin, 256 threads, 8 warps x 16 rows, software-pipelined 4-row batches
// ============================================================================
__global__ __launch_bounds__(256, 4) void kA_vproj(const float* __restrict__ v) {
    const int tid  = threadIdx.x;
    const int wid  = tid >> 5;
    const int lane = tid & 31;
    const float* vb = v + (size_t)blockIdx.x * HW;

    float wxr[4][4];
#pragma unroll
    for (int c = 0; c < 4; c++) {
        float tx = ((lane << 2) + c + 0.5f) * K3;
#pragma unroll
        for (int q = 0; q < 4; q++) wxr[c][q] = hatf(tx - (float)q);
    }

    float acc[16];
#pragma unroll
    for (int t = 0; t < 16; t++) acc[t] = 0.0f;

    float4 cur[4], nxt[4];
#pragma unroll
    for (int j = 0; j < 4; j++)
        cur[j] = *reinterpret_cast<const float4*>(vb + ((wid << 4) + j) * WW + (lane << 2));

#pragma unroll
    for (int bt = 0; bt < 4; bt++) {
        if (bt < 3) {
#pragma unroll
            for (int j = 0; j < 4; j++)
                nxt[j] = *reinterpret_cast<const float4*>(
                    vb + ((wid << 4) + (bt + 1) * 4 + j) * WW + (lane << 2));
        }
#pragma unroll
        for (int j = 0; j < 4; j++) {
            const int r = (wid << 4) + bt * 4 + j;
            float s[4] = {0.f, 0.f, 0.f, 0.f};
            const float vals[4] = {cur[j].x, cur[j].y, cur[j].z, cur[j].w};
#pragma unroll
            for (int c = 0; c < 4; c++) {
#pragma unroll
                for (int q = 0; q < 4; q++) s[q] += vals[c] * wxr[c][q];
            }
            float ty = (r + 0.5f) * K3;
#pragma unroll
            for (int p = 0; p < 4; p++) {
                float hp = hatf(ty - (float)p);
#pragma unroll
                for (int q = 0; q < 4; q++) acc[p * 4 + q] += hp * s[q];
            }
        }
#pragma unroll
        for (int j = 0; j < 4; j++) cur[j] = nxt[j];
    }

#pragma unroll
    for (int t = 0; t < 16; t++) {
#pragma unroll
        for (int off = 16; off > 0; off >>= 1)
            acc[t] += __shfl_xor_sync(0xFFFFFFFFu, acc[t], off);
    }
    __shared__ float red[8][16];
    if (lane == 0) {
#pragma unroll
        for (int t = 0; t < 16; t++) red[wid][t] = acc[t];
    }
    __syncthreads();
    if (tid < 16) {
        float s = 0.f;
#pragma unroll
        for (int w = 0; w < 8; w++) s += red[w][tid];
        g_vproj[blockIdx.x * 16 + tid] = s;
    }
}

// ============================================================================
// Kernel B1 (+ kW merged): grid (33, 8), 256 threads
//  x < 32 : vr[b=y, r=x] = dot(k1[r], vproj[b]) / HW
//  x == 32: split conv_w slice (idx = y*256+tid) into g_Wfrag
// ============================================================================
__global__ __launch_bounds__(256) void kB1W(const float* __restrict__ k1,
                                            const float* __restrict__ cw) {
    const int tid = threadIdx.x;
    if (blockIdx.x == 32) {
        const int idx = blockIdx.y * 256 + tid;   // 0..2047
        const int ot = idx >> 8, ks = (idx >> 5) & 7, lane = idx & 31;
        const int r0 = ot * 16 + (lane >> 2), r1 = r0 + 8;
        const int kb = ks * 16 + (lane & 3) * 2;
        uint32_t hi[4], lo[4];
        split_pack(cw[r0 * CIN + kb],     cw[r0 * CIN + kb + 1], hi[0], lo[0]);
        split_pack(cw[r1 * CIN + kb],     cw[r1 * CIN + kb + 1], hi[1], lo[1]);
        split_pack(cw[r0 * CIN + kb + 8], cw[r0 * CIN + kb + 9], hi[2], lo[2]);
        split_pack(cw[r1 * CIN + kb + 8], cw[r1 * CIN + kb + 9], hi[3], lo[3]);
        g_Wfrag[0][ot][ks][lane] = make_uint4(hi[0], hi[1], hi[2], hi[3]);
        g_Wfrag[1][ot][ks][lane] = make_uint4(lo[0], lo[1], lo[2], lo[3]);
        return;
    }
    const int r = blockIdx.x, b = blockIdx.y;
    const int wid = tid >> 5, lane = tid & 31;
    const float* k1p = k1 + (size_t)r * (CIN * 16);
    const float* vpp = g_vproj + (size_t)b * (CIN * 16);

    float s = 0.f;
#pragma unroll
    for (int j = 0; j < 2; j++) {
        const int e = (j * 256 + tid) * 4;
        float4 a = *reinterpret_cast<const float4*>(k1p + e);
        float4 c = *reinterpret_cast<const float4*>(vpp + e);
        s += a.x * c.x + a.y * c.y + a.z * c.z + a.w * c.w;
    }
#pragma unroll
    for (int off = 16; off > 0; off >>= 1)
        s += __shfl_xor_sync(0xFFFFFFFFu, s, off);
    __shared__ float red[8];
    if (lane == 0) red[wid] = s;
    __syncthreads();
    if (tid == 0) {
        float t = 0.f;
#pragma unroll
        for (int w = 0; w < 8; w++) t += red[w];
        g_vr[b * RNK + r] = t * (1.0f / (float)HW);
    }
}

// ============================================================================
// Kernel B2: partial m over r-chunks of 8: grid (8, 4, B), 256 threads
// ============================================================================
__global__ __launch_bounds__(256) void kB2_m(const float* __restrict__ k2) {
    const int ch = blockIdx.x, rc = blockIdx.y, b = blockIdx.z, tid = threadIdx.x;
    __shared__ float vr[8];
    if (tid < 8) vr[tid] = g_vr[b * RNK + rc * 8 + tid];
    __syncthreads();

    const int idx = ch * 256 + tid;   // 0..2047 over (o,pq)
    float s = 0.f;
#pragma unroll
    for (int j = 0; j < 8; j++)
        s += k2[(size_t)(rc * 8 + j) * (COUT * 16) + idx] * vr[j];
    g_mpart[rc][b * (COUT * 16) + idx] = s;
}

// ============================================================================
// Kernel C: out = conv_w@v (bf16 hi/lo split, tensor cores) + interp(m) + biases
// grid = (h=128, wh=2, b=8), 256 threads; warp tile 32o x 32w
// XOR-swizzled 128B-row smem, double buffered, register prefetch.
// ============================================================================

#define LDSM4T(r0, r1, r2, r3, addr)                                            \
    asm volatile("ldmatrix.sync.aligned.m8n8.x4.trans.shared.b16 {%0,%1,%2,%3}, [%4];" \
                 : "=r"(r0), "=r"(r1), "=r"(r2), "=r"(r3) : "r"(addr))

#define MMA16816(d, a0, a1, a2, a3, b0, b1)                                \
    asm volatile("mma.sync.aligned.m16n8k16.row.col.f32.bf16.bf16.f32 "    \
                 "{%0,%1,%2,%3}, {%4,%5,%6,%7}, {%8,%9}, {%0,%1,%2,%3};"   \
                 : "+f"(d[0]), "+f"(d[1]), "+f"(d[2]), "+f"(d[3])          \
                 : "r"(a0), "r"(a1), "r"(a2), "r"(a3), "r"(b0), "r"(b1))

__global__ __launch_bounds__(256, 3) void kC_main(const float* __restrict__ v,
                                                  const float* __restrict__ conv_b,
                                                  const float* __restrict__ bias,
                                                  float* __restrict__ out) {
    // 32 k-rows x 64 w-cols, 128B rows, 16B chunks XOR-swizzled by (row&7)
    __shared__ __align__(16) __nv_bfloat16 sBhi[2][32][64];
    __shared__ __align__(16) __nv_bfloat16 sBlo[2][32][64];
    __shared__ __align__(16) float sM2[128][4];
    __shared__ float sCB[128];

    const int h = blockIdx.x, wh = blockIdx.y, b = blockIdx.z;
    const int tid = threadIdx.x, wid = tid >> 5, lane = tid & 31;
    const int o_base = (wid & 3) * 32;
    const int wloc   = (wid >> 2) * 32;       // warp's w offset within 64
    const int ot0 = (wid & 3) * 2;

    // thread slot for loads: row li (i), col group lc (8 floats each)
    const int li = tid >> 3;                  // 0..31
    const int lc = tid & 7;                   // 0..7
    const float* vbase = v + (((size_t)b * CIN + li) * HH + h) * WW + wh * 64 + lc * 8;
    const int schunk = lc ^ (li & 7);         // swizzled 16B chunk for stores

    float4 R0 = *reinterpret_cast<const float4*>(vbase);
    float4 R1 = *reinterpret_cast<const float4*>(vbase + 4);

    // prologue: M2[o][q] = sum_p wy[h,p]*m[b,o,p*4+q] (m = sum of 4 partials)
    {
        const float ty = (h + 0.5f) * K3;
        const float wy0 = hatf(ty - 0.f), wy1 = hatf(ty - 1.f);
        const float wy2 = hatf(ty - 2.f), wy3 = hatf(ty - 3.f);
        for (int idx = tid; idx < 512; idx += 256) {
            const int o = idx >> 2, q = idx & 3;
            const int base = b * (COUT * 16) + o * 16 + q;
            float m0 = 0.f, m1 = 0.f, m2 = 0.f, m3 = 0.f;
#pragma unroll
            for (int rc = 0; rc < 4; rc++) {
                const float* mp = &g_mpart[rc][base];
                m0 += mp[0]; m1 += mp[4]; m2 += mp[8]; m3 += mp[12];
            }
            sM2[o][q] = wy0 * m0 + wy1 * m1 + wy2 * m2 + wy3 * m3;
        }
        if (tid < 128) sCB[tid] = conv_b[tid] + bias[tid];
    }

    float acc[2][4][4];
#pragma unroll
    for (int mi = 0; mi < 2; mi++)
#pragma unroll
        for (int ni = 0; ni < 4; ni++)
#pragma unroll
            for (int c = 0; c < 4; c++) acc[mi][ni][c] = 0.0f;

    const uint32_t sHiBase = (uint32_t)__cvta_generic_to_shared(&sBhi[0][0][0]);
    const uint32_t sLoBase = (uint32_t)__cvta_generic_to_shared(&sBlo[0][0][0]);

    for (int kc = 0; kc < 4; kc++) {
        const int buf = kc & 1;
        // convert register chunk -> bf16 hi/lo smem (one STS.128 each)
        {
            uint32_t h0, l0, h1, l1, h2, l2, h3, l3;
            split_pack(R0.x, R0.y, h0, l0);
            split_pack(R0.z, R0.w, h1, l1);
            split_pack(R1.x, R1.y, h2, l2);
            split_pack(R1.z, R1.w, h3, l3);
            *reinterpret_cast<uint4*>(&sBhi[buf][li][schunk * 8]) = make_uint4(h0, h1, h2, h3);
            *reinterpret_cast<uint4*>(&sBlo[buf][li][schunk * 8]) = make_uint4(l0, l1, l2, l3);
        }
        __syncthreads();

        // prefetch next chunk (overlaps MMA)
        if (kc < 3) {
            const float* src = vbase + (size_t)(kc + 1) * 32 * HW;
            R0 = *reinterpret_cast<const float4*>(src);
            R1 = *reinterpret_cast<const float4*>(src + 4);
        }

#pragma unroll
        for (int ks = 0; ks < 2; ks++) {
            const int gks = kc * 2 + ks;
            uint4 AH[2], AL[2];
#pragma unroll
            for (int mi = 0; mi < 2; mi++) {
                AH[mi] = g_Wfrag[0][ot0 + mi][gks][lane];
                AL[mi] = g_Wfrag[1][ot0 + mi][gks][lane];
            }
            const int kr = ks * 16 + (lane & 15);
            const uint32_t rowoff = (uint32_t)(buf * 4096 + kr * 128);
#pragma unroll
            for (int ng = 0; ng < 2; ng++) {
                const int chunk = ((wloc >> 3) + ng * 2 + (lane >> 4)) ^ (kr & 7);
                const uint32_t off = rowoff + chunk * 16;
                uint32_t bh0, bh1, bh2, bh3, bl0, bl1, bl2, bl3;
                LDSM4T(bh0, bh1, bh2, bh3, sHiBase + off);
                LDSM4T(bl0, bl1, bl2, bl3, sLoBase + off);
#pragma unroll
                for (int mi = 0; mi < 2; mi++) {
                    float* d0 = acc[mi][ng * 2 + 0];
                    float* d1 = acc[mi][ng * 2 + 1];
                    MMA16816(d0, AH[mi].x, AH[mi].y, AH[mi].z, AH[mi].w, bh0, bh1);
                    MMA16816(d0, AL[mi].x, AL[mi].y, AL[mi].z, AL[mi].w, bh0, bh1);
                    MMA16816(d0, AH[mi].x, AH[mi].y, AH[mi].z, AH[mi].w, bl0, bl1);
                    MMA16816(d1, AH[mi].x, AH[mi].y, AH[mi].z, AH[mi].w, bh2, bh3);
                    MMA16816(d1, AL[mi].x, AL[mi].y, AL[mi].z, AL[mi].w, bh2, bh3);
                    MMA16816(d1, AH[mi].x, AH[mi].y, AH[mi].z, AH[mi].w, bl2, bl3);
                }
            }
        }
        // double-buffered: next STS goes to the other buffer; reuse of this
        // buffer is ordered by the next iteration's __syncthreads.
    }

    // epilogue: add interp term + biases, store
    const int g = lane >> 2, cq = lane & 3;
#pragma unroll
    for (int ni = 0; ni < 4; ni++) {
        const int w0 = wh * 64 + wloc + ni * 8 + cq * 2;
        const float tx0 = (w0 + 0.5f) * K3, tx1 = tx0 + K3;
        float wxa[4], wxb[4];
#pragma unroll
        for (int q = 0; q < 4; q++) {
            wxa[q] = hatf(tx0 - (float)q);
            wxb[q] = hatf(tx1 - (float)q);
        }
#pragma unroll
        for (int mi = 0; mi < 2; mi++) {
#pragma unroll
            for (int rr = 0; rr < 2; rr++) {
                const int o = o_base + mi * 16 + g + rr * 8;
                float4 m2 = *reinterpret_cast<float4*>(&sM2[o][0]);
                const float base = sCB[o];
                float t0 = base + wxa[0] * m2.x + wxa[1] * m2.y + wxa[2] * m2.z + wxa[3] * m2.w;
                float t1 = base + wxb[0] * m2.x + wxb[1] * m2.y + wxb[2] * m2.z + wxb[3] * m2.w;
                float2 res;
                res.x = acc[mi][ni][rr * 2 + 0] + t0;
                res.y = acc[mi][ni][rr * 2 + 1] + t1;
                *reinterpret_cast<float2*>(out + (((size_t)b * COUT + o) * HH + h) * WW + w0) = res;
            }
        }
    }
}

// ============================================================================
extern "C" void kernel_launch(void* const* d_in, const int* in_sizes, int n_in,
                              void* d_out, int out_size) {
    const float* v      = (const float*)d_in[0];
    const float* k1     = (const float*)d_in[1];
    const float* k2     = (const float*)d_in[2];
    const float* conv_w = (const float*)d_in[3];
    const float* conv_b = (const float*)d_in[4];
    const float* bias   = (const float*)d_in[5];
    float* out = (float*)d_out;

    kA_vproj<<<BB * CIN, 256>>>(v);
    kB1W<<<dim3(33, BB), 256>>>(k1, conv_w);
    kB2_m<<<dim3(8, 4, BB), 256>>>(k2);
    kC_main<<<dim3(HH, 2, BB), 256>>>(v, conv_b, bias, out);
}

// round 7
// speedup vs baseline: 1.2025x; 1.2025x over previous
#include <cuda_runtime.h>
#include <cuda_fp16.h>
#include <cstdint>

// Problem constants
#define BB   8
#define CIN  128
#define COUT 128
#define HH   128
#define WW   128
#define RNK  32
#define HW   (HH*WW)
#define K3   (3.0f/128.0f)

// Scratch (no allocation allowed)
__device__ float g_vproj[BB*CIN*16];      // (b, i, p*4+q)
__device__ float g_vr[BB*RNK];            // (b, r)
__device__ float g_mpart[4][BB*COUT*16];  // partial m over r-chunks
// conv_w as fp16 MMA A-fragments: [o_tile(8)][kstep(8)][lane(32)]
__device__ uint4 g_Wfrag[8][8][32];

__device__ __forceinline__ float hatf(float d) {
    return fmaxf(0.0f, 1.0f - fabsf(d));
}

__device__ __forceinline__ uint32_t packh2(float x, float y) {
    __half2 t = __floats2half2_rn(x, y);
    return *reinterpret_cast<uint32_t*>(&t);
}

// ============================================================================
// Kernel A: vproj[b,i,p,q] = sum_hw wy[h,p]*wx[w,q]*v[b,i,h,w]
// grid = B*Cin, 256 threads, software-pipelined 4-row batches
// ============================================================================
__global__ __launch_bounds__(256, 4) void kA_vproj(const float* __restrict__ v) {
    const int tid  = threadIdx.x;
    const int wid  = tid >> 5;
    const int lane = tid & 31;
    const float* vb = v + (size_t)blockIdx.x * HW;

    float wxr[4][4];
#pragma unroll
    for (int c = 0; c < 4; c++) {
        float tx = ((lane << 2) + c + 0.5f) * K3;
#pragma unroll
        for (int q = 0; q < 4; q++) wxr[c][q] = hatf(tx - (float)q);
    }

    float acc[16];
#pragma unroll
    for (int t = 0; t < 16; t++) acc[t] = 0.0f;

    float4 cur[4], nxt[4];
#pragma unroll
    for (int j = 0; j < 4; j++)
        cur[j] = *reinterpret_cast<const float4*>(vb + ((wid << 4) + j) * WW + (lane << 2));

#pragma unroll
    for (int bt = 0; bt < 4; bt++) {
        if (bt < 3) {
#pragma unroll
            for (int j = 0; j < 4; j++)
                nxt[j] = *reinterpret_cast<const float4*>(
                    vb + ((wid << 4) + (bt + 1) * 4 + j) * WW + (lane << 2));
        }
#pragma unroll
        for (int j = 0; j < 4; j++) {
            const int r = (wid << 4) + bt * 4 + j;
            float s[4] = {0.f, 0.f, 0.f, 0.f};
            const float vals[4] = {cur[j].x, cur[j].y, cur[j].z, cur[j].w};
#pragma unroll
            for (int c = 0; c < 4; c++) {
#pragma unroll
                for (int q = 0; q < 4; q++) s[q] += vals[c] * wxr[c][q];
            }
            float ty = (r + 0.5f) * K3;
#pragma unroll
            for (int p = 0; p < 4; p++) {
                float hp = hatf(ty - (float)p);
#pragma unroll
                for (int q = 0; q < 4; q++) acc[p * 4 + q] += hp * s[q];
            }
        }
#pragma unroll
        for (int j = 0; j < 4; j++) cur[j] = nxt[j];
    }

#pragma unroll
    for (int t = 0; t < 16; t++) {
#pragma unroll
        for (int off = 16; off > 0; off >>= 1)
            acc[t] += __shfl_xor_sync(0xFFFFFFFFu, acc[t], off);
    }
    __shared__ float red[8][16];
    if (lane == 0) {
#pragma unroll
        for (int t = 0; t < 16; t++) red[wid][t] = acc[t];
    }
    __syncthreads();
    if (tid < 16) {
        float s = 0.f;
#pragma unroll
        for (int w = 0; w < 8; w++) s += red[w][tid];
        g_vproj[blockIdx.x * 16 + tid] = s;
    }
}

// ============================================================================
// Kernel B1 (+ W-pack merged): grid (33, 8), 256 threads
//  x < 32 : vr[b=y, r=x] = dot(k1[r], vproj[b]) / HW
//  x == 32: pack conv_w slice into fp16 A-fragments
// ============================================================================
__global__ __launch_bounds__(256) void kB1W(const float* __restrict__ k1,
                                            const float* __restrict__ cw) {
    const int tid = threadIdx.x;
    if (blockIdx.x == 32) {
        const int idx = blockIdx.y * 256 + tid;   // 0..2047
        const int ot = idx >> 8, ks = (idx >> 5) & 7, lane = idx & 31;
        const int r0 = ot * 16 + (lane >> 2), r1 = r0 + 8;
        const int kb = ks * 16 + (lane & 3) * 2;
        uint4 f;
        f.x = packh2(cw[r0 * CIN + kb],     cw[r0 * CIN + kb + 1]);
        f.y = packh2(cw[r1 * CIN + kb],     cw[r1 * CIN + kb + 1]);
        f.z = packh2(cw[r0 * CIN + kb + 8], cw[r0 * CIN + kb + 9]);
        f.w = packh2(cw[r1 * CIN + kb + 8], cw[r1 * CIN + kb + 9]);
        g_Wfrag[ot][ks][lane] = f;
        return;
    }
    const int r = blockIdx.x, b = blockIdx.y;
    const int wid = tid >> 5, lane = tid & 31;
    const float* k1p = k1 + (size_t)r * (CIN * 16);
    const float* vpp = g_vproj + (size_t)b * (CIN * 16);

    float s = 0.f;
#pragma unroll
    for (int j = 0; j < 2; j++) {
        const int e = (j * 256 + tid) * 4;
        float4 a = *reinterpret_cast<const float4*>(k1p + e);
        float4 c = *reinterpret_cast<const float4*>(vpp + e);
        s += a.x * c.x + a.y * c.y + a.z * c.z + a.w * c.w;
    }
#pragma unroll
    for (int off = 16; off > 0; off >>= 1)
        s += __shfl_xor_sync(0xFFFFFFFFu, s, off);
    __shared__ float red[8];
    if (lane == 0) red[wid] = s;
    __syncthreads();
    if (tid == 0) {
        float t = 0.f;
#pragma unroll
        for (int w = 0; w < 8; w++) t += red[w];
        g_vr[b * RNK + r] = t * (1.0f / (float)HW);
    }
}

// ============================================================================
// Kernel B2: partial m over r-chunks of 8: grid (8, 4, B)
// ============================================================================
__global__ __launch_bounds__(256) void kB2_m(const float* __restrict__ k2) {
    const int ch = blockIdx.x, rc = blockIdx.y, b = blockIdx.z, tid = threadIdx.x;
    __shared__ float vr[8];
    if (tid < 8) vr[tid] = g_vr[b * RNK + rc * 8 + tid];
    __syncthreads();

    const int idx = ch * 256 + tid;
    float s = 0.f;
#pragma unroll
    for (int j = 0; j < 8; j++)
        s += k2[(size_t)(rc * 8 + j) * (COUT * 16) + idx] * vr[j];
    g_mpart[rc][b * (COUT * 16) + idx] = s;
}

// ============================================================================
// Kernel C: out = conv_w@v (single-term fp16 HMMA) + interp(m) + biases
// grid = (h=128, b=8), 256 threads (8 warps: 4 o-tiles x 2 w-tiles of 32x64)
// XOR-swizzled 256B-row fp16 smem, double buffered, register prefetch.
// ============================================================================

#define LDSM4T(r0, r1, r2, r3, addr)                                            \
    asm volatile("ldmatrix.sync.aligned.m8n8.x4.trans.shared.b16 {%0,%1,%2,%3}, [%4];" \
                 : "=r"(r0), "=r"(r1), "=r"(r2), "=r"(r3) : "r"(addr))

#define MMAF16(d, a0, a1, a2, a3, b0, b1)                                  \
    asm volatile("mma.sync.aligned.m16n8k16.row.col.f32.f16.f16.f32 "      \
                 "{%0,%1,%2,%3}, {%4,%5,%6,%7}, {%8,%9}, {%0,%1,%2,%3};"   \
                 : "+f"(d[0]), "+f"(d[1]), "+f"(d[2]), "+f"(d[3])          \
                 : "r"(a0), "r"(a1), "r"(a2), "r"(a3), "r"(b0), "r"(b1))

__global__ __launch_bounds__(256, 2) void kC_fp16(const float* __restrict__ v,
                                                  const float* __restrict__ conv_b,
                                                  const float* __restrict__ bias,
                                                  float* __restrict__ out) {
    // 2 bufs x 32 k-rows x 128 w (fp16): 256B rows, 16 chunks of 16B, XOR swizzle
    __shared__ __align__(16) __half sB[2][32][128];
    __shared__ __align__(16) float sM2[128][4];
    __shared__ float sCB[128];

    const int h = blockIdx.x, b = blockIdx.y;
    const int tid = threadIdx.x, wid = tid >> 5, lane = tid & 31;
    const int o_base = (wid & 3) * 32;
    const int w_base = (wid >> 2) * 64;
    const int ot0 = (wid & 3) * 2;

    // load slot: krow = tid>>3 (0..31), seg = tid&7 (16 floats each)
    const int krow = tid >> 3;
    const int seg  = tid & 7;
    const float* vbase = v + (((size_t)b * CIN + krow) * HH + h) * WW + seg * 16;
    const int sw = krow & 7;

    float4 R[4];
#pragma unroll
    for (int j = 0; j < 4; j++) R[j] = *reinterpret_cast<const float4*>(vbase + j * 4);

    // prologue: M2[o][q] = sum_p wy[h,p]*m[b,o,p*4+q] (m = sum of 4 partials)
    {
        const float ty = (h + 0.5f) * K3;
        const float wy0 = hatf(ty), wy1 = hatf(ty - 1.f);
        const float wy2 = hatf(ty - 2.f), wy3 = hatf(ty - 3.f);
        for (int idx = tid; idx < 512; idx += 256) {
            const int o = idx >> 2, q = idx & 3;
            const int base = b * (COUT * 16) + o * 16 + q;
            float m0 = 0.f, m1 = 0.f, m2 = 0.f, m3 = 0.f;
#pragma unroll
            for (int rc = 0; rc < 4; rc++) {
                const float* mp = &g_mpart[rc][base];
                m0 += mp[0]; m1 += mp[4]; m2 += mp[8]; m3 += mp[12];
            }
            sM2[o][q] = wy0 * m0 + wy1 * m1 + wy2 * m2 + wy3 * m3;
        }
        if (tid < 128) sCB[tid] = conv_b[tid] + bias[tid];
    }

    float acc[2][8][4];
#pragma unroll
    for (int mi = 0; mi < 2; mi++)
#pragma unroll
        for (int ni = 0; ni < 8; ni++)
#pragma unroll
            for (int c = 0; c < 4; c++) acc[mi][ni][c] = 0.0f;

    const uint32_t sBbase = (uint32_t)__cvta_generic_to_shared(&sB[0][0][0]);

    for (int kc = 0; kc < 4; kc++) {
        const int buf = kc & 1;
        // convert 16 floats -> 8 half2, two swizzled 16B chunks
        {
            uint32_t u[8];
            u[0] = packh2(R[0].x, R[0].y); u[1] = packh2(R[0].z, R[0].w);
            u[2] = packh2(R[1].x, R[1].y); u[3] = packh2(R[1].z, R[1].w);
            u[4] = packh2(R[2].x, R[2].y); u[5] = packh2(R[2].z, R[2].w);
            u[6] = packh2(R[3].x, R[3].y); u[7] = packh2(R[3].z, R[3].w);
            const uint32_t rowb = sBbase + (uint32_t)(buf * 8192 + krow * 256);
#pragma unroll
            for (int c = 0; c < 2; c++) {
                uint32_t addr = rowb + (uint32_t)(((seg * 2 + c) ^ sw) * 16);
                asm volatile("st.shared.v4.b32 [%0], {%1, %2, %3, %4};"
                             :: "r"(addr), "r"(u[c * 4 + 0]), "r"(u[c * 4 + 1]),
                                "r"(u[c * 4 + 2]), "r"(u[c * 4 + 3]) : "memory");
            }
        }
        __syncthreads();

        // prefetch next chunk (overlaps MMA)
        if (kc < 3) {
            const float* src = vbase + (size_t)(kc + 1) * 32 * HW;
#pragma unroll
            for (int j = 0; j < 4; j++) R[j] = *reinterpret_cast<const float4*>(src + j * 4);
        }

#pragma unroll
        for (int ks = 0; ks < 2; ks++) {
            const int gks = kc * 2 + ks;
            uint4 A0 = g_Wfrag[ot0 + 0][gks][lane];
            uint4 A1 = g_Wfrag[ot0 + 1][gks][lane];
            const int kr = ks * 16 + (lane & 15);
            const uint32_t rowoff = (uint32_t)(buf * 8192 + kr * 256);
            const int cb = (w_base >> 3) + (lane >> 4);    // base chunk + hi/lo 8-col
#pragma unroll
            for (int ng = 0; ng < 4; ng++) {
                const int chunk = (cb + ng * 2) ^ (kr & 7);
                uint32_t b0, b1, b2, b3;
                LDSM4T(b0, b1, b2, b3, sBbase + rowoff + (uint32_t)(chunk * 16));
                float* d00 = acc[0][ng * 2 + 0];
                float* d01 = acc[0][ng * 2 + 1];
                float* d10 = acc[1][ng * 2 + 0];
                float* d11 = acc[1][ng * 2 + 1];
                MMAF16(d00, A0.x, A0.y, A0.z, A0.w, b0, b1);
                MMAF16(d01, A0.x, A0.y, A0.z, A0.w, b2, b3);
                MMAF16(d10, A1.x, A1.y, A1.z, A1.w, b0, b1);
                MMAF16(d11, A1.x, A1.y, A1.z, A1.w, b2, b3);
            }
        }
        // double-buffered: next STS targets the other buffer; reuse is ordered
        // by the following iteration's __syncthreads.
    }

    // epilogue: add interp term + biases, store
    const int g = lane >> 2, cq = lane & 3;
#pragma unroll
    for (int ni = 0; ni < 8; ni++) {
        const int w0 = w_base + ni * 8 + cq * 2;
        const float tx0 = (w0 + 0.5f) * K3, tx1 = tx0 + K3;
        float wxa[4], wxb[4];
#pragma unroll
        for (int q = 0; q < 4; q++) {
            wxa[q] = hatf(tx0 - (float)q);
            wxb[q] = hatf(tx1 - (float)q);
        }
#pragma unroll
        for (int mi = 0; mi < 2; mi++) {
#pragma unroll
            for (int rr = 0; rr < 2; rr++) {
                const int o = o_base + mi * 16 + g + rr * 8;
                float4 m2 = *reinterpret_cast<float4*>(&sM2[o][0]);
                const float base = sCB[o];
                float t0 = base + wxa[0] * m2.x + wxa[1] * m2.y + wxa[2] * m2.z + wxa[3] * m2.w;
                float t1 = base + wxb[0] * m2.x + wxb[1] * m2.y + wxb[2] * m2.z + wxb[3] * m2.w;
                float2 res;
                res.x = acc[mi][ni][rr * 2 + 0] + t0;
                res.y = acc[mi][ni][rr * 2 + 1] + t1;
                *reinterpret_cast<float2*>(out + (((size_t)b * COUT + o) * HH + h) * WW + w0) = res;
            }
        }
    }
}

// ============================================================================
extern "C" void kernel_launch(void* const* d_in, const int* in_sizes, int n_in,
                              void* d_out, int out_size) {
    const float* v      = (const float*)d_in[0];
    const float* k1     = (const float*)d_in[1];
    const float* k2     = (const float*)d_in[2];
    const float* conv_w = (const float*)d_in[3];
    const float* conv_b = (const float*)d_in[4];
    const float* bias   = (const float*)d_in[5];
    float* out = (float*)d_out;

    kA_vproj<<<BB * CIN, 256>>>(v);
    kB1W<<<dim3(33, BB), 256>>>(k1, conv_w);
    kB2_m<<<dim3(8, 4, BB), 256>>>(k2);
    kC_fp16<<<dim3(HH, BB), 256>>>(v, conv_b, bias, out);
}